// round 1
// baseline (speedup 1.0000x reference)
#include <cuda_runtime.h>
#include <cuda_bf16.h>
#include <math.h>

#define BATCH 2048
#define FEW 5
#define NBR 200
#define ED 128
#define DM 256
#define DI 512
#define LH 512
#define G4 2048          // 4*LSTM_HIDDEN
#define NITEMS (2*BATCH + 2*FEW)   // 4106
#define NROWS_SE (BATCH + FEW)     // 2053

// ---------------- scratch (device globals; no allocation allowed) ----------------
__device__ float g_s[(size_t)NITEMS * DM];      // neighbor sums (cat summed over k)
__device__ float g_qn[(size_t)BATCH * DM];      // query_neighbor
__device__ float g_sn[(size_t)FEW * DM];        // support_neighbor
__device__ float g_qg[(size_t)BATCH * DM];      // query_g (post support-encoder)
__device__ float g_sgrows[(size_t)FEW * DM];    // support rows post encoder
__device__ float g_sg[DM];                      // mean support
__device__ float g_spart[G4];                   // support_g @ w_hh[:,256:].T
__device__ float g_xw[(size_t)BATCH * G4];      // q@w_ih.T + b_ih + b_hh
__device__ float g_gates[(size_t)BATCH * G4];   // per-step gates
__device__ float g_h[(size_t)BATCH * DM];       // h (256-dim)
__device__ float g_c[(size_t)BATCH * LH];       // cell state

__device__ __forceinline__ float sigmoidf(float x) { return 1.f / (1.f + __expf(-x)); }

// ---------------- K1: gather + sum over neighbors ----------------
// Block b handles one (sample, side). Thread t: t<128 -> rel col t, t>=128 -> ent col t-128.
__global__ __launch_bounds__(256) void k_gather(
    const int* __restrict__ qlc, const int* __restrict__ qrc,
    const int* __restrict__ slc, const int* __restrict__ src_,
    const float* __restrict__ emb)
{
    __shared__ int ids[NBR * 2];
    int b = blockIdx.x;
    const int* conn; int row;
    if (b < BATCH)               { conn = qlc;  row = b; }
    else if (b < 2*BATCH)        { conn = qrc;  row = b - BATCH; }
    else if (b < 2*BATCH + FEW)  { conn = slc;  row = b - 2*BATCH; }
    else                         { conn = src_; row = b - 2*BATCH - FEW; }
    const int* p = conn + (size_t)row * NBR * 2;
    int t = threadIdx.x;
    for (int i = t; i < NBR * 2; i += 256) ids[i] = p[i];
    __syncthreads();

    int sel = t >> 7;       // 0 = rel, 1 = ent
    int col = t & 127;
    float acc = 0.f;
    #pragma unroll 4
    for (int k = 0; k < NBR; k++) {
        int id = ids[2 * k + sel];
        acc += __ldg(emb + (size_t)id * ED + col);
    }
    g_s[(size_t)b * DM + t] = acc;
}

// ---------------- K2: GCN matvec + bias + deg + tanh + concat placement ----------
// block handles 32 items; threads: i = t&31 (item), j = t>>5 (d-subindex 0..7)
__global__ __launch_bounds__(256) void k_gcn(
    const float* __restrict__ gcn_w, const float* __restrict__ gcn_b,
    const float* __restrict__ qld, const float* __restrict__ qrd,
    const float* __restrict__ sld, const float* __restrict__ srd)
{
    __shared__ float s_tile[32][257];
    __shared__ float w_sm[8][256];
    __shared__ float deg_s[32];
    int t = threadIdx.x;
    int base = blockIdx.x * 32;

    for (int idx = t; idx < 32 * 256; idx += 256) {
        int r = idx >> 8, c = idx & 255;
        int gb = base + r;
        s_tile[r][c] = (gb < NITEMS) ? g_s[(size_t)gb * DM + c] : 0.f;
    }
    if (t < 32) {
        int gb = base + t; float d = 1.f;
        if (gb < BATCH)              d = qld[gb];
        else if (gb < 2*BATCH)       d = qrd[gb - BATCH];
        else if (gb < 2*BATCH + FEW) d = sld[gb - 2*BATCH];
        else if (gb < NITEMS)        d = srd[gb - 2*BATCH - FEW];
        deg_s[t] = d;
    }
    __syncthreads();

    int i = t & 31, j = t >> 5;
    for (int d0 = 0; d0 < ED; d0 += 8) {
        for (int idx = t; idx < 8 * 256; idx += 256) {
            int r = idx >> 8, c = idx & 255;
            w_sm[r][c] = gcn_w[(size_t)(d0 + r) * DM + c];
        }
        __syncthreads();
        float acc = 0.f;
        #pragma unroll 8
        for (int c = 0; c < 256; c++) acc += s_tile[i][c] * w_sm[j][c];
        int gb = base + i;
        if (gb < NITEMS) {
            int d = d0 + j;
            float v = tanhf((acc + 200.f * gcn_b[d]) / deg_s[i]);
            if (gb < BATCH)              g_qn[(size_t)gb * DM + d] = v;
            else if (gb < 2*BATCH)       g_qn[(size_t)(gb - BATCH) * DM + ED + d] = v;
            else if (gb < 2*BATCH + FEW) g_sn[(size_t)(gb - 2*BATCH) * DM + d] = v;
            else                         g_sn[(size_t)(gb - 2*BATCH - FEW) * DM + ED + d] = v;
        }
        __syncthreads();
    }
}

// ---------------- K3: support encoder (MLP + residual + LayerNorm ddof=1) --------
// block: 8 rows, 256 threads (i = t&7 row, j = t>>3 in 0..31)
__global__ __launch_bounds__(256) void k_suppenc(
    const float* __restrict__ W1, const float* __restrict__ b1,
    const float* __restrict__ W2, const float* __restrict__ b2,
    const float* __restrict__ lna, const float* __restrict__ lnb)
{
    __shared__ float Xs[8][257];
    __shared__ float Hs[8][513];
    int t = threadIdx.x;
    int rbase = blockIdx.x * 8;

    for (int idx = t; idx < 8 * 256; idx += 256) {
        int r = idx >> 8, c = idx & 255;
        int gr = rbase + r;
        float v = 0.f;
        if (gr < BATCH)         v = g_qn[(size_t)gr * DM + c];
        else if (gr < NROWS_SE) v = g_sn[(size_t)(gr - BATCH) * DM + c];
        Xs[r][c] = v;
    }
    __syncthreads();

    int i = t & 7, j = t >> 3;   // j: 0..31
    // phase 1: h = relu(X @ W1^T + b1), 512 cols -> 16 per j-thread
    #pragma unroll
    for (int jj = 0; jj < 16; jj++) {
        int col = jj * 32 + j;
        const float* w = W1 + (size_t)col * DM;
        float acc = b1[col];
        for (int c = 0; c < DM; c++) acc += Xs[i][c] * __ldg(w + c);
        Hs[i][col] = fmaxf(acc, 0.f);
    }
    __syncthreads();
    // phase 2: out = h @ W2^T + b2 + X  (store into Xs in place; each elem owned by 1 thread)
    #pragma unroll
    for (int jj = 0; jj < 8; jj++) {
        int col = jj * 32 + j;
        const float* w = W2 + (size_t)col * DI;
        float acc = b2[col] + Xs[i][col];
        for (int c = 0; c < DI; c++) acc += Hs[i][c] * __ldg(w + c);
        Xs[i][col] = acc;
    }
    __syncthreads();
    // phase 3: LayerNorm per row; warp w handles row w
    int warp = t >> 5, lane = t & 31;
    float s = 0.f;
    for (int c = lane; c < DM; c += 32) s += Xs[warp][c];
    #pragma unroll
    for (int o = 16; o; o >>= 1) s += __shfl_xor_sync(0xffffffffu, s, o);
    float mu = s * (1.f / 256.f);
    float v = 0.f;
    for (int c = lane; c < DM; c += 32) { float d = Xs[warp][c] - mu; v += d * d; }
    #pragma unroll
    for (int o = 16; o; o >>= 1) v += __shfl_xor_sync(0xffffffffu, v, o);
    float sigma = sqrtf(v * (1.f / 255.f));        // ddof=1
    float inv = 1.f / (sigma + 0.001f);
    int gr = rbase + warp;
    if (gr < NROWS_SE) {
        float* dst = (gr < BATCH) ? (g_qg + (size_t)gr * DM)
                                  : (g_sgrows + (size_t)(gr - BATCH) * DM);
        for (int c = lane; c < DM; c += 32)
            dst[c] = (Xs[warp][c] - mu) * inv * lna[c] + lnb[c];
    }
}

// ---------------- K4: mean of 5 support rows ----------------
__global__ void k_smean()
{
    int t = threadIdx.x;
    if (t < DM) {
        float a = 0.f;
        #pragma unroll
        for (int r = 0; r < FEW; r++) a += g_sgrows[(size_t)r * DM + t];
        g_sg[t] = a * (1.f / (float)FEW);
    }
}

// ---------------- K5: s_part[j] = dot(sg, w_hh[j, 256:512]) ----------------
__global__ __launch_bounds__(256) void k_spart(const float* __restrict__ whh)
{
    __shared__ float sg_s[DM];
    int t = threadIdx.x;
    sg_s[t] = g_sg[t];
    __syncthreads();
    int j = blockIdx.x * 256 + t;
    const float* wr = whh + (size_t)j * LH + DM;
    float a = 0.f;
    for (int c = 0; c < DM; c++) a += sg_s[c] * __ldg(wr + c);
    g_spart[j] = a;
}

// ---------------- K6: SGEMM  C[2048,2048] = A[2048,256] * B[:, :256]^T + epilogue
// mode 0: A=g_qg, C=g_xw,  add=none,  + vb0[n] + vb1[n]        (b_ih + b_hh)
// mode 1: A=g_h,  C=g_gates, add=g_xw[m][n], + g_spart[n]
// 128x128 tile, BK=16, 256 threads, 8x8 micro-tile, double-buffered
__global__ __launch_bounds__(256) void k_gemm(
    const float* __restrict__ B, int ldb, int mode,
    const float* __restrict__ vb0, const float* __restrict__ vb1)
{
    __shared__ float As[2][16][128];
    __shared__ float Bs[2][16][128];
    const float* A = mode ? g_h : g_qg;
    float* C = mode ? g_gates : g_xw;

    int tid = threadIdx.x;
    int m0 = blockIdx.y * 128;
    int n0 = blockIdx.x * 128;
    int tx = tid & 15;
    int ty = tid >> 4;
    int r0 = tid >> 2;          // 0..63
    int q0 = tid & 3;           // quad within 16-float k-slab

    const float* Aptr0 = A + (size_t)(m0 + r0) * DM + q0 * 4;
    const float* Aptr1 = Aptr0 + (size_t)64 * DM;
    const float* Bptr0 = B + (size_t)(n0 + r0) * ldb + q0 * 4;
    const float* Bptr1 = Bptr0 + (size_t)64 * ldb;

    float acc[8][8];
    #pragma unroll
    for (int i = 0; i < 8; i++)
        #pragma unroll
        for (int j = 0; j < 8; j++) acc[i][j] = 0.f;

    float4 la0, la1, lb0, lb1;
    // prologue: tile 0
    la0 = *(const float4*)(Aptr0);
    la1 = *(const float4*)(Aptr1);
    lb0 = *(const float4*)(Bptr0);
    lb1 = *(const float4*)(Bptr1);
    {
        float av0[4] = {la0.x, la0.y, la0.z, la0.w};
        float av1[4] = {la1.x, la1.y, la1.z, la1.w};
        float bv0[4] = {lb0.x, lb0.y, lb0.z, lb0.w};
        float bv1[4] = {lb1.x, lb1.y, lb1.z, lb1.w};
        #pragma unroll
        for (int e = 0; e < 4; e++) {
            As[0][q0 * 4 + e][r0]      = av0[e];
            As[0][q0 * 4 + e][64 + r0] = av1[e];
            Bs[0][q0 * 4 + e][r0]      = bv0[e];
            Bs[0][q0 * 4 + e][64 + r0] = bv1[e];
        }
    }
    __syncthreads();

    int buf = 0;
    #pragma unroll 1
    for (int kt = 0; kt < 16; kt++) {
        if (kt < 15) {
            int k0 = (kt + 1) * 16;
            la0 = *(const float4*)(Aptr0 + k0);
            la1 = *(const float4*)(Aptr1 + k0);
            lb0 = *(const float4*)(Bptr0 + k0);
            lb1 = *(const float4*)(Bptr1 + k0);
        }
        #pragma unroll
        for (int k = 0; k < 16; k++) {
            float4 af0 = *(const float4*)&As[buf][k][ty * 4];
            float4 af1 = *(const float4*)&As[buf][k][64 + ty * 4];
            float4 bf0 = *(const float4*)&Bs[buf][k][tx * 4];
            float4 bf1 = *(const float4*)&Bs[buf][k][64 + tx * 4];
            float a[8] = {af0.x, af0.y, af0.z, af0.w, af1.x, af1.y, af1.z, af1.w};
            float b[8] = {bf0.x, bf0.y, bf0.z, bf0.w, bf1.x, bf1.y, bf1.z, bf1.w};
            #pragma unroll
            for (int i = 0; i < 8; i++)
                #pragma unroll
                for (int j = 0; j < 8; j++) acc[i][j] += a[i] * b[j];
        }
        if (kt < 15) {
            int nb = buf ^ 1;
            float av0[4] = {la0.x, la0.y, la0.z, la0.w};
            float av1[4] = {la1.x, la1.y, la1.z, la1.w};
            float bv0[4] = {lb0.x, lb0.y, lb0.z, lb0.w};
            float bv1[4] = {lb1.x, lb1.y, lb1.z, lb1.w};
            #pragma unroll
            for (int e = 0; e < 4; e++) {
                As[nb][q0 * 4 + e][r0]      = av0[e];
                As[nb][q0 * 4 + e][64 + r0] = av1[e];
                Bs[nb][q0 * 4 + e][r0]      = bv0[e];
                Bs[nb][q0 * 4 + e][64 + r0] = bv1[e];
            }
        }
        __syncthreads();
        buf ^= 1;
    }

    // epilogue
    #pragma unroll
    for (int i = 0; i < 8; i++) {
        int m = m0 + ((i < 4) ? (ty * 4 + i) : (64 + ty * 4 + i - 4));
        #pragma unroll
        for (int h = 0; h < 2; h++) {
            int n = n0 + h * 64 + tx * 4;
            float4 r;
            r.x = acc[i][h * 4 + 0]; r.y = acc[i][h * 4 + 1];
            r.z = acc[i][h * 4 + 2]; r.w = acc[i][h * 4 + 3];
            if (mode) {
                float4 ad = *(const float4*)(g_xw + (size_t)m * G4 + n);
                r.x += ad.x; r.y += ad.y; r.z += ad.z; r.w += ad.w;
                float4 sp = *(const float4*)(g_spart + n);
                r.x += sp.x; r.y += sp.y; r.z += sp.z; r.w += sp.w;
            } else {
                float4 v0 = *(const float4*)(vb0 + n);
                float4 v1 = *(const float4*)(vb1 + n);
                r.x += v0.x + v1.x; r.y += v0.y + v1.y;
                r.z += v0.z + v1.z; r.w += v0.w + v1.w;
            }
            *(float4*)(C + (size_t)m * G4 + n) = r;
        }
    }
}

// ---------------- K7: LSTM elementwise gate update ----------------
__global__ __launch_bounds__(256) void k_lstm_ew(int first)
{
    const float* gates = first ? g_xw : g_gates;
    int idx = blockIdx.x * 256 + threadIdx.x;   // over 2048*512
    int n = idx >> 9;
    int j = idx & 511;
    const float* g = gates + (size_t)n * G4;
    float gi = g[j], gf = g[LH + j], gg = g[2 * LH + j], go = g[3 * LH + j];
    float c_prev = first ? 0.f : g_c[idx];
    float c = sigmoidf(gf) * c_prev + sigmoidf(gi) * tanhf(gg);
    g_c[idx] = c;
    float h = sigmoidf(go) * tanhf(c);
    if (j < DM) g_h[(size_t)n * DM + j] = g_qg[(size_t)n * DM + j] + h;
}

// ---------------- K8: final scores out[n] = dot(h[n], sg) ----------------
__global__ __launch_bounds__(256) void k_score(float* __restrict__ out)
{
    __shared__ float sg_s[DM];
    int t = threadIdx.x;
    if (t < DM) sg_s[t] = g_sg[t];
    __syncthreads();
    int warp = t >> 5, lane = t & 31;
    int n = blockIdx.x * 8 + warp;
    const float* h = g_h + (size_t)n * DM;
    float a = 0.f;
    #pragma unroll
    for (int c = lane; c < DM; c += 32) a += h[c] * sg_s[c];
    #pragma unroll
    for (int o = 16; o; o >>= 1) a += __shfl_xor_sync(0xffffffffu, a, o);
    if (lane == 0) out[n] = a;
}

// ---------------- launch ----------------
extern "C" void kernel_launch(void* const* d_in, const int* in_sizes, int n_in,
                              void* d_out, int out_size)
{
    const int*   qlc  = (const int*)  d_in[0];
    const float* qld  = (const float*)d_in[1];
    const int*   qrc  = (const int*)  d_in[2];
    const float* qrd  = (const float*)d_in[3];
    const int*   slc  = (const int*)  d_in[4];
    const float* sld  = (const float*)d_in[5];
    const int*   srcontainers = (const int*)d_in[6];
    const float* srd  = (const float*)d_in[7];
    const float* emb  = (const float*)d_in[8];
    const float* gcnw = (const float*)d_in[9];
    const float* gcnb = (const float*)d_in[10];
    const float* p1w  = (const float*)d_in[11];
    const float* p1b  = (const float*)d_in[12];
    const float* p2w  = (const float*)d_in[13];
    const float* p2b  = (const float*)d_in[14];
    const float* lna  = (const float*)d_in[15];
    const float* lnb  = (const float*)d_in[16];
    const float* wih  = (const float*)d_in[17];
    const float* whh  = (const float*)d_in[18];
    const float* bih  = (const float*)d_in[19];
    const float* bhh  = (const float*)d_in[20];
    float* out = (float*)d_out;

    k_gather<<<NITEMS, 256>>>(qlc, qrc, slc, srcontainers, emb);
    k_gcn<<<(NITEMS + 31) / 32, 256>>>(gcnw, gcnb, qld, qrd, sld, srd);
    k_suppenc<<<(NROWS_SE + 7) / 8, 256>>>(p1w, p1b, p2w, p2b, lna, lnb);
    k_smean<<<1, 256>>>();
    k_spart<<<G4 / 256, 256>>>(whh);

    dim3 gg(16, 16);
    // step 1: gates = q@w_ih.T + b_ih + b_hh (h_r = 0)
    k_gemm<<<gg, 256>>>(wih, DM, 0, bih, bhh);
    k_lstm_ew<<<(BATCH * LH) / 256, 256>>>(1);
    // steps 2..4: gates = xw + h@w_hh[:, :256].T + s_part
    for (int s = 0; s < 3; s++) {
        k_gemm<<<gg, 256>>>(whh, LH, 1, nullptr, nullptr);
        k_lstm_ew<<<(BATCH * LH) / 256, 256>>>(0);
    }
    k_score<<<BATCH / 8, 256>>>(out);
}

// round 3
// speedup vs baseline: 1.0498x; 1.0498x over previous
#include <cuda_runtime.h>
#include <cuda_bf16.h>
#include <cstdint>
#include <math.h>

#define BATCH 2048
#define FEW 5
#define NBR 200
#define ED 128
#define DM 256
#define DI 512
#define LH 512
#define G4 2048          // 4*LSTM_HIDDEN
#define NITEMS (2*BATCH + 2*FEW)   // 4106
#define NROWS_SE (BATCH + FEW)     // 2053

// ================= scratch (device globals; no allocation allowed) =========
__device__ float g_s[(size_t)NITEMS * DM];      // neighbor sums
__device__ float g_qn[(size_t)BATCH * DM];      // query_neighbor
__device__ float g_sn[(size_t)FEW * DM];        // support_neighbor
__device__ float g_qg[(size_t)BATCH * DM];      // query_g
__device__ float g_sgrows[(size_t)FEW * DM];    // support rows post encoder
__device__ float g_sg[DM];                      // mean support
__device__ float g_spart[G4];                   // sg @ w_hh[:,256:].T
__device__ float g_xw[(size_t)BATCH * G4];      // q@w_ih.T + b_ih + b_hh
__device__ float g_gates[(size_t)BATCH * G4];   // per-step gates
__device__ float g_h[(size_t)BATCH * DM];       // h (256-dim)
__device__ float g_c[(size_t)BATCH * LH];       // cell state
// bf16 split operands for tensor-core GEMM
__device__ __nv_bfloat16 g_Ah[(size_t)BATCH * DM];
__device__ __nv_bfloat16 g_Al[(size_t)BATCH * DM];
__device__ __nv_bfloat16 g_Bih_h[(size_t)G4 * DM];
__device__ __nv_bfloat16 g_Bih_l[(size_t)G4 * DM];
__device__ __nv_bfloat16 g_Bhh_h[(size_t)G4 * DM];
__device__ __nv_bfloat16 g_Bhh_l[(size_t)G4 * DM];

__device__ __forceinline__ float sigmoidf(float x) { return 1.f / (1.f + __expf(-x)); }
__device__ __forceinline__ void bsplit(float x, __nv_bfloat16& h, __nv_bfloat16& l) {
    h = __float2bfloat16_rn(x);
    l = __float2bfloat16_rn(x - __bfloat162float(h));
}

// ---------------- K1: gather + sum over neighbors ----------------
__global__ __launch_bounds__(256) void k_gather(
    const int* __restrict__ qlc, const int* __restrict__ qrc,
    const int* __restrict__ slc, const int* __restrict__ src_,
    const float* __restrict__ emb)
{
    __shared__ int ids[NBR * 2];
    int b = blockIdx.x;
    const int* conn; int row;
    if (b < BATCH)               { conn = qlc;  row = b; }
    else if (b < 2*BATCH)        { conn = qrc;  row = b - BATCH; }
    else if (b < 2*BATCH + FEW)  { conn = slc;  row = b - 2*BATCH; }
    else                         { conn = src_; row = b - 2*BATCH - FEW; }
    const int* p = conn + (size_t)row * NBR * 2;
    int t = threadIdx.x;
    for (int i = t; i < NBR * 2; i += 256) ids[i] = p[i];
    __syncthreads();

    int sel = t >> 7;
    int col = t & 127;
    float acc = 0.f;
    #pragma unroll 4
    for (int k = 0; k < NBR; k++) {
        int id = ids[2 * k + sel];
        acc += __ldg(emb + (size_t)id * ED + col);
    }
    g_s[(size_t)b * DM + t] = acc;
}

// ---------------- K2: GCN matvec + bias + deg + tanh + concat ----------------
__global__ __launch_bounds__(256) void k_gcn(
    const float* __restrict__ gcn_w, const float* __restrict__ gcn_b,
    const float* __restrict__ qld, const float* __restrict__ qrd,
    const float* __restrict__ sld, const float* __restrict__ srd)
{
    __shared__ float s_tile[32][257];
    __shared__ float w_sm[8][256];
    __shared__ float deg_s[32];
    int t = threadIdx.x;
    int base = blockIdx.x * 32;

    for (int idx = t; idx < 32 * 256; idx += 256) {
        int r = idx >> 8, c = idx & 255;
        int gb = base + r;
        s_tile[r][c] = (gb < NITEMS) ? g_s[(size_t)gb * DM + c] : 0.f;
    }
    if (t < 32) {
        int gb = base + t; float d = 1.f;
        if (gb < BATCH)              d = qld[gb];
        else if (gb < 2*BATCH)       d = qrd[gb - BATCH];
        else if (gb < 2*BATCH + FEW) d = sld[gb - 2*BATCH];
        else if (gb < NITEMS)        d = srd[gb - 2*BATCH - FEW];
        deg_s[t] = d;
    }
    __syncthreads();

    int i = t & 31, j = t >> 5;
    for (int d0 = 0; d0 < ED; d0 += 8) {
        for (int idx = t; idx < 8 * 256; idx += 256) {
            int r = idx >> 8, c = idx & 255;
            w_sm[r][c] = gcn_w[(size_t)(d0 + r) * DM + c];
        }
        __syncthreads();
        float acc = 0.f;
        #pragma unroll 8
        for (int c = 0; c < 256; c++) acc += s_tile[i][c] * w_sm[j][c];
        int gb = base + i;
        if (gb < NITEMS) {
            int d = d0 + j;
            float v = tanhf((acc + 200.f * gcn_b[d]) / deg_s[i]);
            if (gb < BATCH)              g_qn[(size_t)gb * DM + d] = v;
            else if (gb < 2*BATCH)       g_qn[(size_t)(gb - BATCH) * DM + ED + d] = v;
            else if (gb < 2*BATCH + FEW) g_sn[(size_t)(gb - 2*BATCH) * DM + d] = v;
            else                         g_sn[(size_t)(gb - 2*BATCH - FEW) * DM + ED + d] = v;
        }
        __syncthreads();
    }
}

// ---------------- K3: support encoder + fused bf16 split of query_g ----------
__global__ __launch_bounds__(256) void k_suppenc(
    const float* __restrict__ W1, const float* __restrict__ b1,
    const float* __restrict__ W2, const float* __restrict__ b2,
    const float* __restrict__ lna, const float* __restrict__ lnb)
{
    __shared__ float Xs[8][257];
    __shared__ float Hs[8][513];
    int t = threadIdx.x;
    int rbase = blockIdx.x * 8;

    for (int idx = t; idx < 8 * 256; idx += 256) {
        int r = idx >> 8, c = idx & 255;
        int gr = rbase + r;
        float v = 0.f;
        if (gr < BATCH)         v = g_qn[(size_t)gr * DM + c];
        else if (gr < NROWS_SE) v = g_sn[(size_t)(gr - BATCH) * DM + c];
        Xs[r][c] = v;
    }
    __syncthreads();

    int i = t & 7, j = t >> 3;
    #pragma unroll
    for (int jj = 0; jj < 16; jj++) {
        int col = jj * 32 + j;
        const float* w = W1 + (size_t)col * DM;
        float acc = b1[col];
        for (int c = 0; c < DM; c++) acc += Xs[i][c] * __ldg(w + c);
        Hs[i][col] = fmaxf(acc, 0.f);
    }
    __syncthreads();
    #pragma unroll
    for (int jj = 0; jj < 8; jj++) {
        int col = jj * 32 + j;
        const float* w = W2 + (size_t)col * DI;
        float acc = b2[col] + Xs[i][col];
        for (int c = 0; c < DI; c++) acc += Hs[i][c] * __ldg(w + c);
        Xs[i][col] = acc;
    }
    __syncthreads();
    int warp = t >> 5, lane = t & 31;
    float s = 0.f;
    for (int c = lane; c < DM; c += 32) s += Xs[warp][c];
    #pragma unroll
    for (int o = 16; o; o >>= 1) s += __shfl_xor_sync(0xffffffffu, s, o);
    float mu = s * (1.f / 256.f);
    float v = 0.f;
    for (int c = lane; c < DM; c += 32) { float d = Xs[warp][c] - mu; v += d * d; }
    #pragma unroll
    for (int o = 16; o; o >>= 1) v += __shfl_xor_sync(0xffffffffu, v, o);
    float sigma = sqrtf(v * (1.f / 255.f));
    float inv = 1.f / (sigma + 0.001f);
    int gr = rbase + warp;
    if (gr < NROWS_SE) {
        if (gr < BATCH) {
            for (int c = lane; c < DM; c += 32) {
                float val = (Xs[warp][c] - mu) * inv * lna[c] + lnb[c];
                g_qg[(size_t)gr * DM + c] = val;
                __nv_bfloat16 hh, ll; bsplit(val, hh, ll);
                g_Ah[(size_t)gr * DM + c] = hh;
                g_Al[(size_t)gr * DM + c] = ll;
            }
        } else {
            float* dst = g_sgrows + (size_t)(gr - BATCH) * DM;
            for (int c = lane; c < DM; c += 32)
                dst[c] = (Xs[warp][c] - mu) * inv * lna[c] + lnb[c];
        }
    }
}

// ---------------- K4: mean of 5 support rows ----------------
__global__ void k_smean()
{
    int t = threadIdx.x;
    if (t < DM) {
        float a = 0.f;
        #pragma unroll
        for (int r = 0; r < FEW; r++) a += g_sgrows[(size_t)r * DM + t];
        g_sg[t] = a * (1.f / (float)FEW);
    }
}

// ---------------- K5: s_part[j] = dot(sg, w_hh[j, 256:512]) ----------------
__global__ __launch_bounds__(256) void k_spart(const float* __restrict__ whh)
{
    __shared__ float sg_s[DM];
    int t = threadIdx.x;
    sg_s[t] = g_sg[t];
    __syncthreads();
    int j = blockIdx.x * 256 + t;
    const float* wr = whh + (size_t)j * LH + DM;
    float a = 0.f;
    for (int c = 0; c < DM; c++) a += sg_s[c] * __ldg(wr + c);
    g_spart[j] = a;
}

// ---------------- K_convB: fp32 W[:, :256] -> bf16 hi/lo split ----------------
__global__ __launch_bounds__(256) void k_convB(const float* __restrict__ W, int ld, int sel)
{
    __nv_bfloat16* bh = sel ? g_Bhh_h : g_Bih_h;
    __nv_bfloat16* bl = sel ? g_Bhh_l : g_Bih_l;
    int idx = blockIdx.x * 256 + threadIdx.x;     // 2048*64 groups of 4
    int row = idx >> 6, c4 = (idx & 63) << 2;
    float4 v = *(const float4*)(W + (size_t)row * ld + c4);
    float vv[4] = {v.x, v.y, v.z, v.w};
    __nv_bfloat16 h[4], l[4];
    #pragma unroll
    for (int i = 0; i < 4; i++) bsplit(vv[i], h[i], l[i]);
    __nv_bfloat162 h01, h23, l01, l23;
    h01.x = h[0]; h01.y = h[1]; h23.x = h[2]; h23.y = h[3];
    l01.x = l[0]; l01.y = l[1]; l23.x = l[2]; l23.y = l[3];
    __nv_bfloat162* dh = (__nv_bfloat162*)(bh + (size_t)row * DM + c4);
    __nv_bfloat162* dl = (__nv_bfloat162*)(bl + (size_t)row * DM + c4);
    dh[0] = h01; dh[1] = h23;
    dl[0] = l01; dl[1] = l23;
}

// ---------------- K6: HMMA GEMM  C[2048,2048] = A[2048,256] @ B[2048,256]^T
// 3-term bf16 split (AhBh + AhBl + AlBh), fp32 accum via mma.sync m16n8k16.
// CTA 128x128, 8 warps (4m x 2n), warp tile 32x64, K = 3*256 in 24 chunks of 32.
// mode 0: B=w_ih split, C=g_xw,    + vb0[n]+vb1[n]
// mode 1: B=w_hh split, C=g_gates, + g_xw[m][n] + g_spart[n]
#define SMPAD 40   // padded row length (elements); 80B rows -> conflict-free frags
__global__ __launch_bounds__(256) void k_hmma(
    int mode, const float* __restrict__ vb0, const float* __restrict__ vb1)
{
    __shared__ __nv_bfloat16 As[2][128][SMPAD];
    __shared__ __nv_bfloat16 Bs[2][128][SMPAD];

    const __nv_bfloat16* Bh = mode ? g_Bhh_h : g_Bih_h;
    const __nv_bfloat16* Bl = mode ? g_Bhh_l : g_Bih_l;
    float* Cout = mode ? g_gates : g_xw;

    const __nv_bfloat16* Apass[3] = {g_Ah, g_Ah, g_Al};
    const __nv_bfloat16* Bpass[3] = {Bh, Bl, Bh};

    int tid = threadIdx.x, lane = tid & 31, w = tid >> 5;
    int m0 = blockIdx.y * 128, n0 = blockIdx.x * 128;
    int wm = w >> 1, wn = w & 1;

    int lrow = tid >> 1;       // 0..127
    int lq = tid & 1;          // uint4 slots lq and lq+2 (of 4 per row)

    float acc[2][8][4];
    #pragma unroll
    for (int i = 0; i < 2; i++)
        #pragma unroll
        for (int j = 0; j < 8; j++)
            #pragma unroll
            for (int e = 0; e < 4; e++) acc[i][j][e] = 0.f;

    // prologue: load chunk 0 into buffer 0
    {
        const __nv_bfloat16* Ap = Apass[0] + (size_t)(m0 + lrow) * DM;
        const __nv_bfloat16* Bp = Bpass[0] + (size_t)(n0 + lrow) * DM;
        uint4 a0 = *(const uint4*)(Ap + lq * 8);
        uint4 a1 = *(const uint4*)(Ap + (lq + 2) * 8);
        uint4 b0 = *(const uint4*)(Bp + lq * 8);
        uint4 b1 = *(const uint4*)(Bp + (lq + 2) * 8);
        *(uint4*)&As[0][lrow][lq * 8]       = a0;
        *(uint4*)&As[0][lrow][(lq + 2) * 8] = a1;
        *(uint4*)&Bs[0][lrow][lq * 8]       = b0;
        *(uint4*)&Bs[0][lrow][(lq + 2) * 8] = b1;
    }
    __syncthreads();

    #pragma unroll 1
    for (int it = 0; it < 24; it++) {
        int buf = it & 1;
        uint4 ra0, ra1, rb0, rb1;
        if (it + 1 < 24) {
            int p = (it + 1) >> 3;
            int kc = ((it + 1) & 7) * 32;
            const __nv_bfloat16* Ap = Apass[p] + (size_t)(m0 + lrow) * DM + kc;
            const __nv_bfloat16* Bp = Bpass[p] + (size_t)(n0 + lrow) * DM + kc;
            ra0 = *(const uint4*)(Ap + lq * 8);
            ra1 = *(const uint4*)(Ap + (lq + 2) * 8);
            rb0 = *(const uint4*)(Bp + lq * 8);
            rb1 = *(const uint4*)(Bp + (lq + 2) * 8);
        }

        #pragma unroll
        for (int ks = 0; ks < 2; ks++) {
            int k = ks * 16;
            uint32_t afr[2][4];
            #pragma unroll
            for (int mi = 0; mi < 2; mi++) {
                int row = wm * 32 + mi * 16 + (lane >> 2);
                int col = k + (lane & 3) * 2;
                afr[mi][0] = *(const uint32_t*)&As[buf][row][col];
                afr[mi][1] = *(const uint32_t*)&As[buf][row + 8][col];
                afr[mi][2] = *(const uint32_t*)&As[buf][row][col + 8];
                afr[mi][3] = *(const uint32_t*)&As[buf][row + 8][col + 8];
            }
            #pragma unroll
            for (int nj = 0; nj < 8; nj++) {
                int br = wn * 64 + nj * 8 + (lane >> 2);
                int bc = k + (lane & 3) * 2;
                uint32_t b0 = *(const uint32_t*)&Bs[buf][br][bc];
                uint32_t b1 = *(const uint32_t*)&Bs[buf][br][bc + 8];
                #pragma unroll
                for (int mi = 0; mi < 2; mi++) {
                    asm volatile(
                        "mma.sync.aligned.m16n8k16.row.col.f32.bf16.bf16.f32 "
                        "{%0,%1,%2,%3}, {%4,%5,%6,%7}, {%8,%9}, {%0,%1,%2,%3};"
                        : "+f"(acc[mi][nj][0]), "+f"(acc[mi][nj][1]),
                          "+f"(acc[mi][nj][2]), "+f"(acc[mi][nj][3])
                        : "r"(afr[mi][0]), "r"(afr[mi][1]),
                          "r"(afr[mi][2]), "r"(afr[mi][3]),
                          "r"(b0), "r"(b1));
                }
            }
        }

        if (it + 1 < 24) {
            int nb = buf ^ 1;
            *(uint4*)&As[nb][lrow][lq * 8]       = ra0;
            *(uint4*)&As[nb][lrow][(lq + 2) * 8] = ra1;
            *(uint4*)&Bs[nb][lrow][lq * 8]       = rb0;
            *(uint4*)&Bs[nb][lrow][(lq + 2) * 8] = rb1;
        }
        __syncthreads();
    }

    // epilogue
    #pragma unroll
    for (int mi = 0; mi < 2; mi++) {
        int mr = m0 + wm * 32 + mi * 16 + (lane >> 2);
        #pragma unroll
        for (int nj = 0; nj < 8; nj++) {
            int cc = n0 + wn * 64 + nj * 8 + ((lane & 3) << 1);
            float d0 = acc[mi][nj][0], d1 = acc[mi][nj][1];
            float d2 = acc[mi][nj][2], d3 = acc[mi][nj][3];
            if (mode) {
                float2 sp = *(const float2*)(g_spart + cc);
                float2 x0 = *(const float2*)(g_xw + (size_t)mr * G4 + cc);
                float2 x1 = *(const float2*)(g_xw + (size_t)(mr + 8) * G4 + cc);
                d0 += x0.x + sp.x; d1 += x0.y + sp.y;
                d2 += x1.x + sp.x; d3 += x1.y + sp.y;
            } else {
                float2 v0 = *(const float2*)(vb0 + cc);
                float2 v1 = *(const float2*)(vb1 + cc);
                d0 += v0.x + v1.x; d1 += v0.y + v1.y;
                d2 += v0.x + v1.x; d3 += v0.y + v1.y;
            }
            float2 o0; o0.x = d0; o0.y = d1;
            float2 o1; o1.x = d2; o1.y = d3;
            *(float2*)(Cout + (size_t)mr * G4 + cc) = o0;
            *(float2*)(Cout + (size_t)(mr + 8) * G4 + cc) = o1;
        }
    }
}

// ---------------- K7: LSTM elementwise + fused bf16 split of h ----------------
__global__ __launch_bounds__(256) void k_lstm_ew(int first)
{
    const float* gates = first ? g_xw : g_gates;
    int idx = blockIdx.x * 256 + threadIdx.x;   // over 2048*512
    int n = idx >> 9;
    int j = idx & 511;
    const float* g = gates + (size_t)n * G4;
    float gi = g[j], gf = g[LH + j], gg = g[2 * LH + j], go = g[3 * LH + j];
    float c_prev = first ? 0.f : g_c[idx];
    float c = sigmoidf(gf) * c_prev + sigmoidf(gi) * tanhf(gg);
    g_c[idx] = c;
    if (j < DM) {
        float hv = g_qg[(size_t)n * DM + j] + sigmoidf(go) * tanhf(c);
        g_h[(size_t)n * DM + j] = hv;
        __nv_bfloat16 hh, ll; bsplit(hv, hh, ll);
        g_Ah[(size_t)n * DM + j] = hh;
        g_Al[(size_t)n * DM + j] = ll;
    }
}

// ---------------- K8: final scores out[n] = dot(h[n], sg) ----------------
__global__ __launch_bounds__(256) void k_score(float* __restrict__ out)
{
    __shared__ float sg_s[DM];
    int t = threadIdx.x;
    if (t < DM) sg_s[t] = g_sg[t];
    __syncthreads();
    int warp = t >> 5, lane = t & 31;
    int n = blockIdx.x * 8 + warp;
    const float* h = g_h + (size_t)n * DM;
    float a = 0.f;
    #pragma unroll
    for (int c = lane; c < DM; c += 32) a += h[c] * sg_s[c];
    #pragma unroll
    for (int o = 16; o; o >>= 1) a += __shfl_xor_sync(0xffffffffu, a, o);
    if (lane == 0) out[n] = a;
}

// ---------------- launch ----------------
extern "C" void kernel_launch(void* const* d_in, const int* in_sizes, int n_in,
                              void* d_out, int out_size)
{
    const int*   qlc  = (const int*)  d_in[0];
    const float* qld  = (const float*)d_in[1];
    const int*   qrc  = (const int*)  d_in[2];
    const float* qrd  = (const float*)d_in[3];
    const int*   slc  = (const int*)  d_in[4];
    const float* sld  = (const float*)d_in[5];
    const int*   src_ = (const int*)  d_in[6];
    const float* srd  = (const float*)d_in[7];
    const float* emb  = (const float*)d_in[8];
    const float* gcnw = (const float*)d_in[9];
    const float* gcnb = (const float*)d_in[10];
    const float* p1w  = (const float*)d_in[11];
    const float* p1b  = (const float*)d_in[12];
    const float* p2w  = (const float*)d_in[13];
    const float* p2b  = (const float*)d_in[14];
    const float* lna  = (const float*)d_in[15];
    const float* lnb  = (const float*)d_in[16];
    const float* wih  = (const float*)d_in[17];
    const float* whh  = (const float*)d_in[18];
    const float* bih  = (const float*)d_in[19];
    const float* bhh  = (const float*)d_in[20];
    float* out = (float*)d_out;

    k_convB<<<512, 256>>>(wih, DM, 0);
    k_convB<<<512, 256>>>(whh, LH, 1);
    k_gather<<<NITEMS, 256>>>(qlc, qrc, slc, src_, emb);
    k_gcn<<<(NITEMS + 31) / 32, 256>>>(gcnw, gcnb, qld, qrd, sld, srd);
    k_suppenc<<<(NROWS_SE + 7) / 8, 256>>>(p1w, p1b, p2w, p2b, lna, lnb);
    k_smean<<<1, 256>>>();
    k_spart<<<G4 / 256, 256>>>(whh);

    dim3 gg(16, 16);   // n-tiles x m-tiles
    // step 1: xw = q@w_ih.T + b_ih + b_hh (h_r = 0)
    k_hmma<<<gg, 256>>>(0, bih, bhh);
    k_lstm_ew<<<(BATCH * LH) / 256, 256>>>(1);
    // steps 2..4: gates = xw + h@w_hh[:, :256].T + s_part
    for (int s = 0; s < 3; s++) {
        k_hmma<<<gg, 256>>>(1, nullptr, nullptr);
        k_lstm_ew<<<(BATCH * LH) / 256, 256>>>(0);
    }
    k_score<<<BATCH / 8, 256>>>(out);
}

// round 4
// speedup vs baseline: 1.5672x; 1.4929x over previous
#include <cuda_runtime.h>
#include <cuda_bf16.h>
#include <cstdint>
#include <math.h>

#define BATCH 2048
#define FEW 5
#define NBR 200
#define ED 128
#define DM 256
#define DI 512
#define LH 512
#define G4 2048          // 4*LSTM_HIDDEN
#define NITEMS (2*BATCH + 2*FEW)   // 4106
#define NROWS_SE (BATCH + FEW)     // 2053
#define MPAD_S 4224      // NITEMS padded to 128
#define MPAD_X 2176      // NROWS_SE padded to 128

// ================= scratch (device globals; zero-initialized) =========
__device__ float g_qg[(size_t)BATCH * DM];      // query_g (fp32, LSTM residual)
__device__ float g_sgrows[(size_t)FEW * DM];    // support rows post encoder
__device__ float g_sg[DM];                      // mean support
__device__ float g_spart[G4];                   // sg @ w_hh[:,256:].T
__device__ float g_xw[(size_t)BATCH * G4];      // q@w_ih.T + b_ih + b_hh
__device__ float g_gates[(size_t)BATCH * G4];   // per-step gates
__device__ float g_h[(size_t)BATCH * DM];       // h (256-dim)
__device__ float g_c[(size_t)BATCH * LH];       // cell state
__device__ float g_deg[MPAD_S];                 // degrees per item

// bf16 split operands
__device__ __nv_bfloat16 g_Sh[(size_t)MPAD_S * DM];   // neighbor sums split
__device__ __nv_bfloat16 g_Sl[(size_t)MPAD_S * DM];
__device__ __nv_bfloat16 g_Xh[(size_t)MPAD_X * DM];   // concat tanh output split
__device__ __nv_bfloat16 g_Xl[(size_t)MPAD_X * DM];
__device__ float         g_X32[(size_t)MPAD_X * DM];  // fp32 X (residual)
__device__ __nv_bfloat16 g_Hh[(size_t)MPAD_X * DI];   // relu hidden split
__device__ __nv_bfloat16 g_Hl[(size_t)MPAD_X * DI];
__device__ float         g_out32[(size_t)MPAD_X * DM];// pre-LN output
__device__ __nv_bfloat16 g_Ah[(size_t)BATCH * DM];    // LSTM A operand split
__device__ __nv_bfloat16 g_Al[(size_t)BATCH * DM];
__device__ __nv_bfloat16 g_Bih_h[(size_t)G4 * DM];
__device__ __nv_bfloat16 g_Bih_l[(size_t)G4 * DM];
__device__ __nv_bfloat16 g_Bhh_h[(size_t)G4 * DM];
__device__ __nv_bfloat16 g_Bhh_l[(size_t)G4 * DM];
__device__ __nv_bfloat16 g_Wgh[(size_t)ED * DM];
__device__ __nv_bfloat16 g_Wgl[(size_t)ED * DM];
__device__ __nv_bfloat16 g_W1h[(size_t)DI * DM];
__device__ __nv_bfloat16 g_W1l[(size_t)DI * DM];
__device__ __nv_bfloat16 g_W2h[(size_t)DM * DI];
__device__ __nv_bfloat16 g_W2l[(size_t)DM * DI];

__device__ __forceinline__ float sigmoidf(float x) { return 1.f / (1.f + __expf(-x)); }
__device__ __forceinline__ void bsplit(float x, __nv_bfloat16& h, __nv_bfloat16& l) {
    h = __float2bfloat16_rn(x);
    l = __float2bfloat16_rn(x - __bfloat162float(h));
}

// ---------------- K1: gather + sum over neighbors (writes bf16 split + deg) ----
__global__ __launch_bounds__(256) void k_gather(
    const int* __restrict__ qlc, const int* __restrict__ qrc,
    const int* __restrict__ slc, const int* __restrict__ src_,
    const float* __restrict__ emb,
    const float* __restrict__ qld, const float* __restrict__ qrd,
    const float* __restrict__ sld, const float* __restrict__ srd)
{
    __shared__ int ids[NBR * 2];
    int b = blockIdx.x;
    const int* conn; const float* degp; int row;
    if (b < BATCH)               { conn = qlc;  degp = qld; row = b; }
    else if (b < 2*BATCH)        { conn = qrc;  degp = qrd; row = b - BATCH; }
    else if (b < 2*BATCH + FEW)  { conn = slc;  degp = sld; row = b - 2*BATCH; }
    else                         { conn = src_; degp = srd; row = b - 2*BATCH - FEW; }
    const int* p = conn + (size_t)row * NBR * 2;
    int t = threadIdx.x;
    for (int i = t; i < NBR * 2; i += 256) ids[i] = p[i];
    if (t == 0) g_deg[b] = degp[row];
    __syncthreads();

    int sel = t >> 7;
    int col = t & 127;
    float acc = 0.f;
    #pragma unroll 4
    for (int k = 0; k < NBR; k++) {
        int id = ids[2 * k + sel];
        acc += __ldg(emb + (size_t)id * ED + col);
    }
    __nv_bfloat16 hh, ll; bsplit(acc, hh, ll);
    g_Sh[(size_t)b * DM + t] = hh;
    g_Sl[(size_t)b * DM + t] = ll;
}

// ---------------- K_convB: fp32 W[:, :256] -> bf16 hi/lo split (row extract) ----
__global__ __launch_bounds__(256) void k_convB(const float* __restrict__ W, int ld, int sel)
{
    __nv_bfloat16* bh = sel ? g_Bhh_h : g_Bih_h;
    __nv_bfloat16* bl = sel ? g_Bhh_l : g_Bih_l;
    int idx = blockIdx.x * 256 + threadIdx.x;     // 2048*64 groups of 4
    int row = idx >> 6, c4 = (idx & 63) << 2;
    float4 v = *(const float4*)(W + (size_t)row * ld + c4);
    float vv[4] = {v.x, v.y, v.z, v.w};
    __nv_bfloat16 h[4], l[4];
    #pragma unroll
    for (int i = 0; i < 4; i++) bsplit(vv[i], h[i], l[i]);
    __nv_bfloat162 h01, h23, l01, l23;
    h01.x = h[0]; h01.y = h[1]; h23.x = h[2]; h23.y = h[3];
    l01.x = l[0]; l01.y = l[1]; l23.x = l[2]; l23.y = l[3];
    __nv_bfloat162* dh = (__nv_bfloat162*)(bh + (size_t)row * DM + c4);
    __nv_bfloat162* dl = (__nv_bfloat162*)(bl + (size_t)row * DM + c4);
    dh[0] = h01; dh[1] = h23;
    dl[0] = l01; dl[1] = l23;
}

// ---------------- K_convW: contiguous fp32 -> bf16 hi/lo split ----------------
__global__ __launch_bounds__(256) void k_convW(
    const float* __restrict__ W, __nv_bfloat16* __restrict__ bh,
    __nv_bfloat16* __restrict__ bl)
{
    int idx = blockIdx.x * 256 + threadIdx.x;
    int c4 = idx << 2;
    float4 v = *(const float4*)(W + c4);
    float vv[4] = {v.x, v.y, v.z, v.w};
    __nv_bfloat16 h[4], l[4];
    #pragma unroll
    for (int i = 0; i < 4; i++) bsplit(vv[i], h[i], l[i]);
    __nv_bfloat162 h01, h23, l01, l23;
    h01.x = h[0]; h01.y = h[1]; h23.x = h[2]; h23.y = h[3];
    l01.x = l[0]; l01.y = l[1]; l23.x = l[2]; l23.y = l[3];
    *(__nv_bfloat162*)(bh + c4)     = h01;
    *(__nv_bfloat162*)(bh + c4 + 2) = h23;
    *(__nv_bfloat162*)(bl + c4)     = l01;
    *(__nv_bfloat162*)(bl + c4 + 2) = l23;
}

// ---------------- generic HMMA GEMM: C[M,N] = A[M,K] @ B[N,K]^T ----------------
// 3-term bf16 split (AhBh + AhBl + AlBh), fp32 accum via mma.sync m16n8k16.
// CTA 128x128, 8 warps (4m x 2n), warp tile 32x64, double-buffered smem.
// modes:
//  0: C=g_xw,    d += e0[n]+e1[n]
//  1: C=g_gates, d += g_xw[m][n] + g_spart[n]
//  2: gcn:  v=tanh((d+200*e0[n])/deg[m]); scatter concat -> g_X32/g_Xh/g_Xl
//  3: mlp1: v=relu(d+e0[n]) -> g_Hh/g_Hl
//  4: mlp2: v=d+e0[n]+g_X32[m][n] -> g_out32
#define SMPAD 40
__global__ __launch_bounds__(256) void k_hmma(
    const __nv_bfloat16* __restrict__ Ah, const __nv_bfloat16* __restrict__ Al,
    const __nv_bfloat16* __restrict__ Bh, const __nv_bfloat16* __restrict__ Bl,
    int K, int mode, const float* __restrict__ e0, const float* __restrict__ e1)
{
    __shared__ __nv_bfloat16 As[2][128][SMPAD];
    __shared__ __nv_bfloat16 Bs[2][128][SMPAD];

    const __nv_bfloat16* Apass[3] = {Ah, Ah, Al};
    const __nv_bfloat16* Bpass[3] = {Bh, Bl, Bh};

    int tid = threadIdx.x, lane = tid & 31, w = tid >> 5;
    int m0 = blockIdx.y * 128, n0 = blockIdx.x * 128;
    int wm = w >> 1, wn = w & 1;

    int lrow = tid >> 1;       // 0..127
    int lq = tid & 1;          // uint4 slots lq and lq+2 (of 4 per 32-elem chunk)

    int kchunks = K >> 5;
    int nchunks = 3 * kchunks;

    float acc[2][8][4];
    #pragma unroll
    for (int i = 0; i < 2; i++)
        #pragma unroll
        for (int j = 0; j < 8; j++)
            #pragma unroll
            for (int e = 0; e < 4; e++) acc[i][j][e] = 0.f;

    // prologue: chunk 0 into buffer 0
    {
        const __nv_bfloat16* Ap = Apass[0] + (size_t)(m0 + lrow) * K;
        const __nv_bfloat16* Bp = Bpass[0] + (size_t)(n0 + lrow) * K;
        uint4 a0 = *(const uint4*)(Ap + lq * 8);
        uint4 a1 = *(const uint4*)(Ap + (lq + 2) * 8);
        uint4 b0 = *(const uint4*)(Bp + lq * 8);
        uint4 b1 = *(const uint4*)(Bp + (lq + 2) * 8);
        *(uint4*)&As[0][lrow][lq * 8]       = a0;
        *(uint4*)&As[0][lrow][(lq + 2) * 8] = a1;
        *(uint4*)&Bs[0][lrow][lq * 8]       = b0;
        *(uint4*)&Bs[0][lrow][(lq + 2) * 8] = b1;
    }
    __syncthreads();

    #pragma unroll 1
    for (int it = 0; it < nchunks; it++) {
        int buf = it & 1;
        uint4 ra0, ra1, rb0, rb1;
        if (it + 1 < nchunks) {
            int nit = it + 1;
            int p = nit / kchunks;
            int kc = (nit - p * kchunks) * 32;
            const __nv_bfloat16* Ap = Apass[p] + (size_t)(m0 + lrow) * K + kc;
            const __nv_bfloat16* Bp = Bpass[p] + (size_t)(n0 + lrow) * K + kc;
            ra0 = *(const uint4*)(Ap + lq * 8);
            ra1 = *(const uint4*)(Ap + (lq + 2) * 8);
            rb0 = *(const uint4*)(Bp + lq * 8);
            rb1 = *(const uint4*)(Bp + (lq + 2) * 8);
        }

        #pragma unroll
        for (int ks = 0; ks < 2; ks++) {
            int k = ks * 16;
            uint32_t afr[2][4];
            #pragma unroll
            for (int mi = 0; mi < 2; mi++) {
                int row = wm * 32 + mi * 16 + (lane >> 2);
                int col = k + (lane & 3) * 2;
                afr[mi][0] = *(const uint32_t*)&As[buf][row][col];
                afr[mi][1] = *(const uint32_t*)&As[buf][row + 8][col];
                afr[mi][2] = *(const uint32_t*)&As[buf][row][col + 8];
                afr[mi][3] = *(const uint32_t*)&As[buf][row + 8][col + 8];
            }
            #pragma unroll
            for (int nj = 0; nj < 8; nj++) {
                int br = wn * 64 + nj * 8 + (lane >> 2);
                int bc = k + (lane & 3) * 2;
                uint32_t b0 = *(const uint32_t*)&Bs[buf][br][bc];
                uint32_t b1 = *(const uint32_t*)&Bs[buf][br][bc + 8];
                #pragma unroll
                for (int mi = 0; mi < 2; mi++) {
                    asm volatile(
                        "mma.sync.aligned.m16n8k16.row.col.f32.bf16.bf16.f32 "
                        "{%0,%1,%2,%3}, {%4,%5,%6,%7}, {%8,%9}, {%0,%1,%2,%3};"
                        : "+f"(acc[mi][nj][0]), "+f"(acc[mi][nj][1]),
                          "+f"(acc[mi][nj][2]), "+f"(acc[mi][nj][3])
                        : "r"(afr[mi][0]), "r"(afr[mi][1]),
                          "r"(afr[mi][2]), "r"(afr[mi][3]),
                          "r"(b0), "r"(b1));
                }
            }
        }

        if (it + 1 < nchunks) {
            int nb = buf ^ 1;
            *(uint4*)&As[nb][lrow][lq * 8]       = ra0;
            *(uint4*)&As[nb][lrow][(lq + 2) * 8] = ra1;
            *(uint4*)&Bs[nb][lrow][lq * 8]       = rb0;
            *(uint4*)&Bs[nb][lrow][(lq + 2) * 8] = rb1;
        }
        __syncthreads();
    }

    // ---------------- epilogues ----------------
    if (mode == 0 || mode == 1) {
        float* Cout = mode ? g_gates : g_xw;
        #pragma unroll
        for (int mi = 0; mi < 2; mi++) {
            int mr = m0 + wm * 32 + mi * 16 + (lane >> 2);
            #pragma unroll
            for (int nj = 0; nj < 8; nj++) {
                int cc = n0 + wn * 64 + nj * 8 + ((lane & 3) << 1);
                float d0 = acc[mi][nj][0], d1 = acc[mi][nj][1];
                float d2 = acc[mi][nj][2], d3 = acc[mi][nj][3];
                if (mode) {
                    float2 sp = *(const float2*)(g_spart + cc);
                    float2 x0 = *(const float2*)(g_xw + (size_t)mr * G4 + cc);
                    float2 x1 = *(const float2*)(g_xw + (size_t)(mr + 8) * G4 + cc);
                    d0 += x0.x + sp.x; d1 += x0.y + sp.y;
                    d2 += x1.x + sp.x; d3 += x1.y + sp.y;
                } else {
                    float2 v0 = *(const float2*)(e0 + cc);
                    float2 v1 = *(const float2*)(e1 + cc);
                    d0 += v0.x + v1.x; d1 += v0.y + v1.y;
                    d2 += v0.x + v1.x; d3 += v0.y + v1.y;
                }
                float2 o0; o0.x = d0; o0.y = d1;
                float2 o1; o1.x = d2; o1.y = d3;
                *(float2*)(Cout + (size_t)mr * G4 + cc) = o0;
                *(float2*)(Cout + (size_t)(mr + 8) * G4 + cc) = o1;
            }
        }
    } else if (mode == 2) {
        #pragma unroll
        for (int mi = 0; mi < 2; mi++) {
            int r0 = m0 + wm * 32 + mi * 16 + (lane >> 2);
            #pragma unroll
            for (int rr = 0; rr < 2; rr++) {
                int gb = r0 + rr * 8;
                if (gb >= NITEMS) continue;
                float dg = g_deg[gb];
                int r2, cb;
                if (gb < BATCH)                { r2 = gb;                        cb = 0; }
                else if (gb < 2*BATCH)         { r2 = gb - BATCH;                cb = ED; }
                else if (gb < 2*BATCH + FEW)   { r2 = BATCH + gb - 2*BATCH;      cb = 0; }
                else                           { r2 = BATCH + gb - 2*BATCH - FEW; cb = ED; }
                #pragma unroll
                for (int nj = 0; nj < 8; nj++) {
                    int cc = n0 + wn * 64 + nj * 8 + ((lane & 3) << 1);  // 0..127
                    float v0 = tanhf((acc[mi][nj][rr * 2 + 0] + 200.f * e0[cc])     / dg);
                    float v1 = tanhf((acc[mi][nj][rr * 2 + 1] + 200.f * e0[cc + 1]) / dg);
                    size_t off = (size_t)r2 * DM + cb + cc;
                    g_X32[off] = v0; g_X32[off + 1] = v1;
                    __nv_bfloat16 h0, l0, h1, l1;
                    bsplit(v0, h0, l0); bsplit(v1, h1, l1);
                    g_Xh[off] = h0; g_Xh[off + 1] = h1;
                    g_Xl[off] = l0; g_Xl[off + 1] = l1;
                }
            }
        }
    } else if (mode == 3) {
        #pragma unroll
        for (int mi = 0; mi < 2; mi++) {
            int r0 = m0 + wm * 32 + mi * 16 + (lane >> 2);
            #pragma unroll
            for (int rr = 0; rr < 2; rr++) {
                int mr = r0 + rr * 8;
                #pragma unroll
                for (int nj = 0; nj < 8; nj++) {
                    int cc = n0 + wn * 64 + nj * 8 + ((lane & 3) << 1);
                    float v0 = fmaxf(acc[mi][nj][rr * 2 + 0] + e0[cc], 0.f);
                    float v1 = fmaxf(acc[mi][nj][rr * 2 + 1] + e0[cc + 1], 0.f);
                    size_t off = (size_t)mr * DI + cc;
                    __nv_bfloat16 h0, l0, h1, l1;
                    bsplit(v0, h0, l0); bsplit(v1, h1, l1);
                    g_Hh[off] = h0; g_Hh[off + 1] = h1;
                    g_Hl[off] = l0; g_Hl[off + 1] = l1;
                }
            }
        }
    } else { // mode 4
        #pragma unroll
        for (int mi = 0; mi < 2; mi++) {
            int r0 = m0 + wm * 32 + mi * 16 + (lane >> 2);
            #pragma unroll
            for (int rr = 0; rr < 2; rr++) {
                int mr = r0 + rr * 8;
                #pragma unroll
                for (int nj = 0; nj < 8; nj++) {
                    int cc = n0 + wn * 64 + nj * 8 + ((lane & 3) << 1);
                    size_t off = (size_t)mr * DM + cc;
                    float2 xr = *(const float2*)(g_X32 + off);
                    float2 o;
                    o.x = acc[mi][nj][rr * 2 + 0] + e0[cc]     + xr.x;
                    o.y = acc[mi][nj][rr * 2 + 1] + e0[cc + 1] + xr.y;
                    *(float2*)(g_out32 + off) = o;
                }
            }
        }
    }
}

// ---------------- K_ln: LayerNorm (ddof=1) + split/query-support scatter -------
__global__ __launch_bounds__(256) void k_ln(
    const float* __restrict__ lna, const float* __restrict__ lnb)
{
    int t = threadIdx.x;
    int warp = t >> 5, lane = t & 31;
    int gr = blockIdx.x * 8 + warp;
    if (gr >= NROWS_SE) return;
    const float* x = g_out32 + (size_t)gr * DM;
    float xs[8];
    float s = 0.f;
    #pragma unroll
    for (int i = 0; i < 8; i++) { xs[i] = x[lane + i * 32]; s += xs[i]; }
    #pragma unroll
    for (int o = 16; o; o >>= 1) s += __shfl_xor_sync(0xffffffffu, s, o);
    float mu = s * (1.f / 256.f);
    float v = 0.f;
    #pragma unroll
    for (int i = 0; i < 8; i++) { float d = xs[i] - mu; v += d * d; }
    #pragma unroll
    for (int o = 16; o; o >>= 1) v += __shfl_xor_sync(0xffffffffu, v, o);
    float sigma = sqrtf(v * (1.f / 255.f));
    float inv = 1.f / (sigma + 0.001f);
    if (gr < BATCH) {
        #pragma unroll
        for (int i = 0; i < 8; i++) {
            int c = lane + i * 32;
            float val = (xs[i] - mu) * inv * lna[c] + lnb[c];
            g_qg[(size_t)gr * DM + c] = val;
            __nv_bfloat16 hh, ll; bsplit(val, hh, ll);
            g_Ah[(size_t)gr * DM + c] = hh;
            g_Al[(size_t)gr * DM + c] = ll;
        }
    } else {
        float* dst = g_sgrows + (size_t)(gr - BATCH) * DM;
        #pragma unroll
        for (int i = 0; i < 8; i++) {
            int c = lane + i * 32;
            dst[c] = (xs[i] - mu) * inv * lna[c] + lnb[c];
        }
    }
}

// ---------------- K4: mean of 5 support rows ----------------
__global__ void k_smean()
{
    int t = threadIdx.x;
    if (t < DM) {
        float a = 0.f;
        #pragma unroll
        for (int r = 0; r < FEW; r++) a += g_sgrows[(size_t)r * DM + t];
        g_sg[t] = a * (1.f / (float)FEW);
    }
}

// ---------------- K5: s_part[j] = dot(sg, w_hh[j, 256:512]) ----------------
__global__ __launch_bounds__(256) void k_spart(const float* __restrict__ whh)
{
    __shared__ float sg_s[DM];
    int t = threadIdx.x;
    sg_s[t] = g_sg[t];
    __syncthreads();
    int j = blockIdx.x * 256 + t;
    const float* wr = whh + (size_t)j * LH + DM;
    float a = 0.f;
    for (int c = 0; c < DM; c++) a += sg_s[c] * __ldg(wr + c);
    g_spart[j] = a;
}

// ---------------- K7: LSTM elementwise + fused bf16 split of h ----------------
__global__ __launch_bounds__(256) void k_lstm_ew(int first)
{
    const float* gates = first ? g_xw : g_gates;
    int idx = blockIdx.x * 256 + threadIdx.x;   // over 2048*512
    int n = idx >> 9;
    int j = idx & 511;
    const float* g = gates + (size_t)n * G4;
    float gi = g[j], gf = g[LH + j], gg = g[2 * LH + j], go = g[3 * LH + j];
    float c_prev = first ? 0.f : g_c[idx];
    float c = sigmoidf(gf) * c_prev + sigmoidf(gi) * tanhf(gg);
    g_c[idx] = c;
    if (j < DM) {
        float hv = g_qg[(size_t)n * DM + j] + sigmoidf(go) * tanhf(c);
        g_h[(size_t)n * DM + j] = hv;
        __nv_bfloat16 hh, ll; bsplit(hv, hh, ll);
        g_Ah[(size_t)n * DM + j] = hh;
        g_Al[(size_t)n * DM + j] = ll;
    }
}

// ---------------- K8: final scores out[n] = dot(h[n], sg) ----------------
__global__ __launch_bounds__(256) void k_score(float* __restrict__ out)
{
    __shared__ float sg_s[DM];
    int t = threadIdx.x;
    if (t < DM) sg_s[t] = g_sg[t];
    __syncthreads();
    int warp = t >> 5, lane = t & 31;
    int n = blockIdx.x * 8 + warp;
    const float* h = g_h + (size_t)n * DM;
    float a = 0.f;
    #pragma unroll
    for (int c = lane; c < DM; c += 32) a += h[c] * sg_s[c];
    #pragma unroll
    for (int o = 16; o; o >>= 1) a += __shfl_xor_sync(0xffffffffu, a, o);
    if (lane == 0) out[n] = a;
}

// ---------------- launch ----------------
extern "C" void kernel_launch(void* const* d_in, const int* in_sizes, int n_in,
                              void* d_out, int out_size)
{
    const int*   qlc  = (const int*)  d_in[0];
    const float* qld  = (const float*)d_in[1];
    const int*   qrc  = (const int*)  d_in[2];
    const float* qrd  = (const float*)d_in[3];
    const int*   slc  = (const int*)  d_in[4];
    const float* sld  = (const float*)d_in[5];
    const int*   src_ = (const int*)  d_in[6];
    const float* srd  = (const float*)d_in[7];
    const float* emb  = (const float*)d_in[8];
    const float* gcnw = (const float*)d_in[9];
    const float* gcnb = (const float*)d_in[10];
    const float* p1w  = (const float*)d_in[11];
    const float* p1b  = (const float*)d_in[12];
    const float* p2w  = (const float*)d_in[13];
    const float* p2b  = (const float*)d_in[14];
    const float* lna  = (const float*)d_in[15];
    const float* lnb  = (const float*)d_in[16];
    const float* wih  = (const float*)d_in[17];
    const float* whh  = (const float*)d_in[18];
    const float* bih  = (const float*)d_in[19];
    const float* bhh  = (const float*)d_in[20];
    float* out = (float*)d_out;

    // weight conversions
    k_convB<<<512, 256>>>(wih, DM, 0);
    k_convB<<<512, 256>>>(whh, LH, 1);
    __nv_bfloat16 *wgh, *wgl, *w1h, *w1l, *w2h, *w2l;
    cudaGetSymbolAddress((void**)&wgh, g_Wgh); cudaGetSymbolAddress((void**)&wgl, g_Wgl);
    cudaGetSymbolAddress((void**)&w1h, g_W1h); cudaGetSymbolAddress((void**)&w1l, g_W1l);
    cudaGetSymbolAddress((void**)&w2h, g_W2h); cudaGetSymbolAddress((void**)&w2l, g_W2l);
    k_convW<<<32, 256>>>(gcnw, wgh, wgl);      // 128*256
    k_convW<<<128, 256>>>(p1w, w1h, w1l);      // 512*256
    k_convW<<<128, 256>>>(p2w, w2h, w2l);      // 256*512

    // gather (launch #6 -> ncu -s 5 captures this)
    k_gather<<<NITEMS, 256>>>(qlc, qrc, slc, src_, emb, qld, qrd, sld, srd);

    __nv_bfloat16 *sh, *sl, *xh, *xl, *hh2, *hl2, *ah, *al, *bih_h, *bih_l, *bhh_h, *bhh_l;
    cudaGetSymbolAddress((void**)&sh, g_Sh);   cudaGetSymbolAddress((void**)&sl, g_Sl);
    cudaGetSymbolAddress((void**)&xh, g_Xh);   cudaGetSymbolAddress((void**)&xl, g_Xl);
    cudaGetSymbolAddress((void**)&hh2, g_Hh);  cudaGetSymbolAddress((void**)&hl2, g_Hl);
    cudaGetSymbolAddress((void**)&ah, g_Ah);   cudaGetSymbolAddress((void**)&al, g_Al);
    cudaGetSymbolAddress((void**)&bih_h, g_Bih_h); cudaGetSymbolAddress((void**)&bih_l, g_Bih_l);
    cudaGetSymbolAddress((void**)&bhh_h, g_Bhh_h); cudaGetSymbolAddress((void**)&bhh_l, g_Bhh_l);

    // GCN as GEMM: [4224,256] x [128,256]^T, tanh/deg/scatter epilogue
    k_hmma<<<dim3(1, MPAD_S / 128), 256>>>(sh, sl, wgh, wgl, 256, 2, gcnb, nullptr);
    // support-encoder MLP
    k_hmma<<<dim3(4, MPAD_X / 128), 256>>>(xh, xl, w1h, w1l, 256, 3, p1b, nullptr);
    k_hmma<<<dim3(2, MPAD_X / 128), 256>>>(hh2, hl2, w2h, w2l, 512, 4, p2b, nullptr);
    k_ln<<<(NROWS_SE + 7) / 8, 256>>>(lna, lnb);
    k_smean<<<1, 256>>>();
    k_spart<<<G4 / 256, 256>>>(whh);

    // LSTM steps
    k_hmma<<<dim3(16, 16), 256>>>(ah, al, bih_h, bih_l, 256, 0, bih, bhh);
    k_lstm_ew<<<(BATCH * LH) / 256, 256>>>(1);
    for (int s = 0; s < 3; s++) {
        k_hmma<<<dim3(16, 16), 256>>>(ah, al, bhh_h, bhh_l, 256, 1, nullptr, nullptr);
        k_lstm_ew<<<(BATCH * LH) / 256, 256>>>(0);
    }
    k_score<<<BATCH / 8, 256>>>(out);
}